// round 16
// baseline (speedup 1.0000x reference)
#include <cuda_runtime.h>
#include <cstdint>

#define KK 1000
#define BB 64
#define MAXIT 50
#define NBLK_S 64         // one batch row per block (64 < 148 SMs: all co-resident)
#define NTHR_S 128
#define EPT 8             // 128 threads * 8 = 1024 >= 1000
#define NTHR_P 256
#define ROWS_PER 10
#define BV_STRIDE 1008    // padded row stride so (b*1008+3+1+4t) is 16B aligned

// ---------------- device scratch (no allocations allowed) ----------------
__device__ float g_A[BB*KK];            // A_i = e2_i / s2          (in [0,1])
__device__ float g_Bv[BB*BV_STRIDE];    // B_j = e1_j * e^20 * s2   (in [0,1]); stored at +3 offset
__device__ float g_ot[BB];
__device__ float g_ce[BB];
__device__ unsigned g_slot[MAXIT];      // packed: low16 = arrivals, high16 = converged count

// ---------------- block reduction macros (4 warps) -----------------------
// Buffer-reuse safety: any two consecutive reduction sites use different
// buffers, so the single barrier per site is sufficient.
#define RSUM(valv, buf, outv) do {                                         \
    float _v = (valv);                                                     \
    _Pragma("unroll")                                                      \
    for (int _o=16; _o; _o>>=1) _v += __shfl_xor_sync(0xffffffffu,_v,_o);  \
    if (lane==0) buf[warp] = _v;                                           \
    __syncthreads();                                                       \
    outv = (buf[0]+buf[1])+(buf[2]+buf[3]);                                \
} while(0)

#define RMAXR(valv, buf, outv) do {                                        \
    float _v = (valv);                                                     \
    _Pragma("unroll")                                                      \
    for (int _o=16; _o; _o>>=1) _v = fmaxf(_v,__shfl_xor_sync(0xffffffffu,_v,_o)); \
    if (lane==0) buf[warp] = _v;                                           \
    __syncthreads();                                                       \
    outv = fmaxf(fmaxf(buf[0],buf[1]),fmaxf(buf[2],buf[3]));               \
} while(0)

// ---------------- kernel 1: persistent Sinkhorn, 1 row/block -------------
// Two-pass: pass A evolves state locally and lazily discovers the global
// stop iteration T (never blocking on other blocks); pass B reruns exactly
// T iterations with identical arithmetic order and zero sync overhead.
__global__ void __launch_bounds__(NTHR_S) sinkhorn_kernel(
    const float* __restrict__ SL, const float* __restrict__ TL,
    const int* __restrict__ labels)
{
    __shared__ float bufA[4], bufB[4];
    __shared__ float bufMx[4], bufMn[4];
    __shared__ float bufC[4], bufD[4];
    __shared__ unsigned sh_T;

    const int t    = threadIdx.x;
    const int warp = t >> 5;
    const int lane = t & 31;
    const int b    = blockIdx.x;
    const int base = t * EPT;
    const bool valid = (base < KK);   // uniform per thread; last 3 threads are pads
    const float* sl = SL + b*KK;
    const float* tl = TL + b*KK;

    const float LOGC = -18.420680743952367f;     // log(1e-8)
    const float LAM  = 2.0611536224385579e-09f;  // e^-20
    const float E20  = 4.85165195409790278e8f;   // e^20
    const float SH   = 20.0f;                    // fixed logsumexp shift

    // ---- setup: log-probs @ TEMP=4, clamped ----
    float x[EPT], la[EPT], lb[EPT];

    if (valid){
        float4 a0 = *(const float4*)(tl + base);
        float4 a1 = *(const float4*)(tl + base + 4);
        x[0]=a0.x*0.25f; x[1]=a0.y*0.25f; x[2]=a0.z*0.25f; x[3]=a0.w*0.25f;
        x[4]=a1.x*0.25f; x[5]=a1.y*0.25f; x[6]=a1.z*0.25f; x[7]=a1.w*0.25f;
    } else {
#pragma unroll
        for (int k=0;k<EPT;k++) x[k] = -1e30f;
    }
    {
        float m = x[0], s;
#pragma unroll
        for (int k=1;k<EPT;k++) m = fmaxf(m, x[k]);
        RMAXR(m, bufA, m);
        float sl_ = 0.f;
#pragma unroll
        for (int k=0;k<EPT;k++) sl_ += __expf(x[k]-m);
        RSUM(sl_, bufB, s);
        float lz = m + __logf(s);
#pragma unroll
        for (int k=0;k<EPT;k++) la[k] = valid ? fmaxf(x[k]-lz, LOGC) : -1e30f;
    }
    if (valid){
        float4 a0 = *(const float4*)(sl + base);
        float4 a1 = *(const float4*)(sl + base + 4);
        x[0]=a0.x*0.25f; x[1]=a0.y*0.25f; x[2]=a0.z*0.25f; x[3]=a0.w*0.25f;
        x[4]=a1.x*0.25f; x[5]=a1.y*0.25f; x[6]=a1.z*0.25f; x[7]=a1.w*0.25f;
    }
    {
        float m = x[0], s;
#pragma unroll
        for (int k=1;k<EPT;k++) m = fmaxf(m, x[k]);
        RMAXR(m, bufA, m);
        float sl_ = 0.f;
#pragma unroll
        for (int k=0;k<EPT;k++) sl_ += __expf(x[k]-m);
        RSUM(sl_, bufB, s);
        float lz = m + __logf(s);
#pragma unroll
        for (int k=0;k<EPT;k++) lb[k] = valid ? fmaxf(x[k]-lz, LOGC) : -1e30f;
    }

    // state: e1 = exp(g+lb-SH), e2 = exp(f+la-SH); P,Q folded exponentials
    float P[EPT], Q[EPT], e1[EPT], e2[EPT], inv1p[EPT];
#pragma unroll
    for (int k=0;k<EPT;k++){
        Q[k]     = __expf(la[k] - 2.f*SH);    // la-40 >= -65 -> normal
        P[k]     = __expf(lb[k] - 2.f*SH);
        e1[k]    = __expf(lb[k] - SH);        // g=0 init
        inv1p[k] = E20;                       // 1/w1_old with f_old=0 -> w1_old=e^-SH
    }

    // =================== PASS A: local evolution + lazy T discovery =======
    // t0 posts one packed atomic per iteration (fire-and-forget) and scans
    // completed slots with a lazy pointer: one non-blocking volatile load per
    // iteration, consumed the NEXT iteration (latency fully hidden). Never
    // spin-waits inside the loop -> no cross-block latency on critical path.
    if (t == 0) sh_T = 0u;                    // ordered before first RSUM barrier
    int      scanp  = 0;
    unsigned pend   = 0;
    bool     havep  = false;

    for (int it = 0; it < MAXIT; ++it){
        float s1l = ((e1[0]+e1[1])+(e1[2]+e1[3]))+((e1[4]+e1[5])+(e1[6]+e1[7]));
        float s1;
        RSUM(s1l, bufA, s1);                  // barrier also publishes sh_T
        if (sh_T) break;                      // T known: stop evolving

        // f-step: w1 = e1 + LAM*s1; e2 = Q/w1; ratio r tracks |f_new - f_old|
        float A1 = LAM * s1;
        float s2l = 0.f, rmx = 0.f, rmn = 1e30f;
#pragma unroll
        for (int k=0;k<EPT;k++){
            float w1  = e1[k] + A1;
            float inv = __fdividef(1.f, w1);
            float e2k = Q[k] * inv;
            float r   = w1 * inv1p[k];        // w1_new / w1_old
            inv1p[k]  = inv;
            e2[k]     = e2k;
            s2l      += e2k;
            rmx = fmaxf(rmx, r);
            rmn = fminf(rmn, r);
        }
        if (!valid){ rmx = 1.f; rmn = 1.f; }  // pads excluded from err

        // fused triple reduce: sum + max + min
#pragma unroll
        for (int o=16;o;o>>=1){
            s2l += __shfl_xor_sync(0xffffffffu, s2l, o);
            rmx  = fmaxf(rmx, __shfl_xor_sync(0xffffffffu, rmx, o));
            rmn  = fminf(rmn, __shfl_xor_sync(0xffffffffu, rmn, o));
        }
        if (lane==0){ bufB[warp]=s2l; bufMx[warp]=rmx; bufMn[warp]=rmn; }
        __syncthreads();
        float s2 = (bufB[0]+bufB[1])+(bufB[2]+bufB[3]);

        if (t == 0){
            float RX = fmaxf(fmaxf(bufMx[0],bufMx[1]), fmaxf(bufMx[2],bufMx[3]));
            float RN = fminf(fminf(bufMn[0],bufMn[1]), fminf(bufMn[2],bufMn[3]));
            float err = fmaxf(fabsf(__logf(RX)), fabsf(__logf(RN)));
            atomicAdd(&g_slot[it], 1u + ((err < 1e-3f) ? 0x10000u : 0u));

            // lazy scan step: consume last iteration's load, issue next one
            if (havep){
                unsigned v = pend;
                if ((v & 0xFFFFu) == (unsigned)NBLK_S){
                    if ((v >> 16) == (unsigned)NBLK_S) sh_T = (unsigned)(scanp + 1);
                    else scanp++;
                }
            }
            pend  = *(volatile unsigned*)&g_slot[scanp];
            havep = true;
        }

        // g-step: e1 = P / (e2 + LAM*s2)   (no barrier needed)
        float A2 = LAM * s2;
#pragma unroll
        for (int k=0;k<EPT;k++){
            float w2 = e2[k] + A2;
            e1[k] = P[k] * __fdividef(1.f, w2);
        }
    }

    // ---- resolve T definitively (post-scan only spins on slots that are
    // guaranteed to complete: every block executes >= T iterations) ----
    if (t == 0){
        unsigned T = sh_T;
        if (T == 0u){
            for (; scanp < MAXIT; ++scanp){
                unsigned v;
                do { v = *(volatile unsigned*)&g_slot[scanp]; }
                while ((v & 0xFFFFu) < (unsigned)NBLK_S);
                if ((v >> 16) == (unsigned)NBLK_S){ T = (unsigned)(scanp + 1); break; }
            }
            if (T == 0u) T = (unsigned)MAXIT;
        }
        sh_T = T;
    }
    __syncthreads();
    const int T = (int)sh_T;

    // =================== PASS B: rerun exactly T iterations, zero sync ====
    // Identical arithmetic and reduction order -> bit-identical trajectory.
#pragma unroll
    for (int k=0;k<EPT;k++) e1[k] = P[k] * E20;   // e1_init = exp(lb-SH)

    float s2 = 0.f;
    for (int j = 0; j < T; ++j){
        float s1l = ((e1[0]+e1[1])+(e1[2]+e1[3]))+((e1[4]+e1[5])+(e1[6]+e1[7]));
        float s1;
        RSUM(s1l, bufA, s1);
        float A1 = LAM * s1;
        float s2l = 0.f;
#pragma unroll
        for (int k=0;k<EPT;k++){
            float w1  = e1[k] + A1;
            float inv = __fdividef(1.f, w1);
            float e2k = Q[k] * inv;
            e2[k] = e2k;
            s2l  += e2k;
        }
        RSUM(s2l, bufB, s2);
        float A2 = LAM * s2;
#pragma unroll
        for (int k=0;k<EPT;k++){
            float w2 = e2[k] + A2;
            e1[k] = P[k] * __fdividef(1.f, w2);
        }
    }

    // ---- epilogue ----
    // s2/e2 from final f-step; e1 from final g-step. pi_off = e2_i*e1_j*e^20.
    float s1fl = 0.f, El = 0.f;
#pragma unroll
    for (int k=0;k<EPT;k++){ s1fl += e1[k]; El += e1[k]*e2[k]; }
#pragma unroll
    for (int o=16;o;o>>=1){
        s1fl += __shfl_xor_sync(0xffffffffu, s1fl, o);
        El   += __shfl_xor_sync(0xffffffffu, El,   o);
    }
    if (lane==0){ bufC[warp]=s1fl; bufD[warp]=El; }
    __syncthreads();
    float s1f = (bufC[0]+bufC[1])+(bufC[2]+bufC[3]);
    float E   = (bufD[0]+bufD[1])+(bufD[2]+bufD[3]);

    // factors: A = e2/s2 (<=1), B = e1*e^20*s2 (<=1); A*B = off-diag pi, diag *e^20
    float rs2 = __fdividef(1.f, s2);
    float cB  = E20 * s2;
    if (valid){
        float* pa = g_A + b*KK + base;
        *(float4*)(pa)   = make_float4(e2[0]*rs2, e2[1]*rs2, e2[2]*rs2, e2[3]*rs2);
        *(float4*)(pa+4) = make_float4(e2[4]*rs2, e2[5]*rs2, e2[6]*rs2, e2[7]*rs2);
        float* pb = g_Bv + b*BV_STRIDE + 3 + base;   // +3 mirrors output misalignment
#pragma unroll
        for (int k=0;k<EPT;k++) pb[k] = e1[k]*cB;
    }

    // CE at temperature 1 (reload raw logits; still L2-resident)
    if (valid){
        float4 a0 = *(const float4*)(sl + base);
        float4 a1 = *(const float4*)(sl + base + 4);
        x[0]=a0.x; x[1]=a0.y; x[2]=a0.z; x[3]=a0.w;
        x[4]=a1.x; x[5]=a1.y; x[6]=a1.z; x[7]=a1.w;
    } else {
#pragma unroll
        for (int k=0;k<EPT;k++) x[k] = -1e30f;
    }
    float ms = x[0], zs;
#pragma unroll
    for (int k=1;k<EPT;k++) ms = fmaxf(ms, x[k]);
    RMAXR(ms, bufB, ms);
    float zl = 0.f;
#pragma unroll
    for (int k=0;k<EPT;k++) zl += __expf(x[k]-ms);
    RSUM(zl, bufA, zs);

    if (t == 0){
        g_ot[b] = E20 * (s1f*s2 - E);   // e^20*(Σe1*Σe2 − Σe1e2) = off-diag mass
        g_ce[b] = -(sl[labels[b]] - ms - __logf(zs));
    }
}

// ---------------- kernel 2: plan writer + finalize + slot reset ----------
__global__ void __launch_bounds__(NTHR_P, 8) planfin_kernel(float* __restrict__ out)
{
    float* __restrict__ outp = out + 3;
    const int blk = blockIdx.x;
    const int b   = blk / (KK/ROWS_PER);
    const int i0  = (blk % (KK/ROWS_PER)) * ROWS_PER;
    const int t   = threadIdx.x;
    const float R = 4.85165195409790278e8f;   // e^20 diagonal fixup

    if (blk == 0){
        if (t < MAXIT) g_slot[t] = 0u;        // reset sync state for next replay
        if (t >= 64 && t < 96){               // warp 2: finalize losses
            int l = t - 64;
            float ot = g_ot[l] + g_ot[l+32];
            float ce = g_ce[l] + g_ce[l+32];
#pragma unroll
            for (int o=16;o;o>>=1){
                ot += __shfl_xor_sync(0xffffffffu, ot, o);
                ce += __shfl_xor_sync(0xffffffffu, ce, o);
            }
            if (l == 0){
                float OT = ot * (1.0f/64.0f);
                float CE = ce * (1.0f/64.0f);
                out[0] = CE + 0.5f*OT;   // total_loss
                out[1] = OT;             // ot_loss
                out[2] = CE;             // ce_loss
            }
        }
    }

    const float* __restrict__ evr = g_Bv + b*BV_STRIDE + 3;   // B_j at j, 16B aligned at j0
    const float* __restrict__ eur = g_A  + b*KK;

    // per-thread invariant ev slice in registers
    float4 er = make_float4(0.f,0.f,0.f,0.f);
    const int j0 = 1 + 4*t;
    if (t < 249) er = *(const float4*)(evr + j0);
    float ese = 0.f; int js = -1;
    if (t >= 249 && t < 253){
        js  = (t == 252) ? 0 : (997 + (t - 249));
        ese = evr[js];
    }

#pragma unroll
    for (int r = 0; r < ROWS_PER; r++){
        const int i = i0 + r;
        const float eu = eur[i];                       // uniform broadcast load
        float* p = outp + (size_t)(b*KK + i) * KK;     // p+j0 is 16B aligned
        if (t < 249){
            float4 v;
            v.x = eu*er.x; v.y = eu*er.y; v.z = eu*er.z; v.w = eu*er.w;
            unsigned d = (unsigned)(i - j0);
            if (d < 4u) ((float*)&v)[d] *= R;          // diagonal fixup
            __stcs(reinterpret_cast<float4*>(p + j0), v);
        } else if (t < 253){
            float v = eu * ese;
            if (js == i) v *= R;
            __stcs(p + js, v);
        }
    }
}

// ---------------- launch ----------------
extern "C" void kernel_launch(void* const* d_in, const int* in_sizes, int n_in,
                              void* d_out, int out_size)
{
    const float* sl     = (const float*)d_in[0];  // student_logits [64,1000]
    const float* tl     = (const float*)d_in[1];  // teacher_logits [64,1000]
    const int*   labels = (const int*)d_in[2];    // labels [64]
    // d_in[3] = C, structure known analytically (1 - I), unused
    float* out = (float*)d_out;                   // [3 + 64*1000*1000]

    sinkhorn_kernel<<<NBLK_S, NTHR_S>>>(sl, tl, labels);
    planfin_kernel<<<BB*(KK/ROWS_PER), NTHR_P>>>(out);
}